// round 15
// baseline (speedup 1.0000x reference)
#include <cuda_runtime.h>
#include <cuda_bf16.h>
#include <cstdint>

// ---- feature gate: tcgen05 only exists in arch-accelerated / family passes ----
#if defined(__CUDA_ARCH__) && (defined(__CUDA_ARCH_FEAT_SM103_ALL) || \
                               defined(__CUDA_ARCH_FEAT_SM100_ALL) || \
                               defined(__CUDA_ARCH_FEAT_SM101_ALL) || \
                               (defined(__CUDA_ARCH_FAMILY_SPECIFIC__) && \
                                (__CUDA_ARCH_FAMILY_SPECIFIC__ == 1000 || \
                                 __CUDA_ARCH_FAMILY_SPECIFIC__ == 1010 || \
                                 __CUDA_ARCH_FAMILY_SPECIFIC__ == 1030)))
#define HAS_TC 1
#else
#define HAS_TC 0
#endif

// ---------------- problem constants ----------------
#define BATCH   8
#define GRIDW   24
#define CCH     768
#define NPATCH  (BATCH*GRIDW*GRIDW)   // 4608
#define KDIM    1024
#define NMEM    20000
#define NMEM_PAD 20224                // 79*256
#define IMG     384

// ---------------- cg2 GEMM tiling: cluster tile M=512 x N=256 ----------------
#define TILE_M   512
#define TILE_N   256
#define TILE_K   64
#define NSTAGE   4
#define MT_TILES (NPATCH/TILE_M)      // 9
#define NT_TILES (NMEM_PAD/TILE_N)    // 79
#define NTILES   (MT_TILES*NT_TILES)  // 711
#define KCHUNKS  (KDIM/TILE_K)        // 16

#define A_HALF      16384
#define STAGE_BYTES (3*A_HALF)        // 49152

#define NTHREADS 416                  // 8 epi + 4 producer + 1 mma warps

#define SMEM_MNORM   (NSTAGE*STAGE_BYTES)      // 196608, 2KB (lt-parity buffers)
#define SMEM_BAR     (SMEM_MNORM + 2048)
#define SMEM_TMEMPTR (SMEM_BAR + 96)
#define SMEM_DYN     (SMEM_TMEMPTR + 16 + 1024)

#define GEMM_IDESC ((1u<<4)|(1u<<7)|(1u<<10)|((TILE_N/8u)<<17)|((256u/16u)<<24))

// embed smem: one layer's [768][6] floats (layer-chunked)
#define EMB_SMEM (768*6*4)            // 18432

// ---------------- scratch ----------------
__device__ __nv_bfloat16 g_mb[(size_t)NMEM_PAD * KDIM];
__device__ float         g_mnorm[NMEM_PAD];
__device__ __nv_bfloat16 g_emb[(size_t)NPATCH * KDIM];
__device__ float         g_enorm[NPATCH];
__device__ float         g_pscores[NPATCH];

// ---------------- common helpers ----------------
__device__ __forceinline__ uint32_t smem_u32(const void* p) {
    uint32_t a;
    asm("{ .reg .u64 t; cvta.to.shared.u64 t, %1; cvt.u32.u64 %0, t; }" : "=r"(a) : "l"(p));
    return a;
}
__device__ __forceinline__ void cp16(uint32_t dst, const void* src) {
    asm volatile("cp.async.cg.shared.global [%0], [%1], 16;" :: "r"(dst), "l"(src));
}
#define SW128X(o) ((o) ^ (((o) >> 3) & 0x70))

#if HAS_TC
__device__ __forceinline__ void mbar_init(uint32_t a, uint32_t c) {
    asm volatile("mbarrier.init.shared.b64 [%0], %1;" :: "r"(a), "r"(c) : "memory");
}
__device__ __forceinline__ void mbar_arrive_rank0(uint32_t a) {
    asm volatile(
        "{\n\t.reg .b32 rem;\n\t"
        "mapa.shared::cluster.u32 rem, %0, 0;\n\t"
        "mbarrier.arrive.shared::cluster.b64 _, [rem];\n\t}"
        :: "r"(a) : "memory");
}
__device__ __forceinline__ void mbar_wait(uint32_t a, uint32_t parity) {
    asm volatile(
        "{\n\t.reg .pred P;\n"
        "WL_%=:\n\t"
        "mbarrier.try_wait.parity.acquire.cta.shared::cta.b64 P, [%0], %1, 0x989680;\n\t"
        "@P bra.uni WD_%=;\n\t"
        "bra.uni WL_%=;\n"
        "WD_%=:\n\t}"
        :: "r"(a), "r"(parity) : "memory");
}
__device__ __forceinline__ bool elect1() {
    uint32_t p;
    asm volatile("{\n\t.reg .pred P;\n\telect.sync _|P, 0xFFFFFFFF;\n\tselp.b32 %0,1,0,P;\n\t}" : "=r"(p));
    return p != 0;
}
__device__ __forceinline__ uint32_t ctarank() {
    uint32_t r; asm("mov.u32 %0, %%cluster_ctarank;" : "=r"(r)); return r;
}
__device__ __forceinline__ uint64_t mk_desc_sw128(uint32_t addr) {
    return ((uint64_t)2 << 61) | ((uint64_t)1 << 46) | ((uint64_t)64 << 32) |
           ((uint64_t)1 << 16) | (((uint64_t)addr >> 4) & 0x3FFF);
}
__device__ __forceinline__ void mma_f16_ss_cg2(uint32_t d, uint64_t a, uint64_t b,
                                               uint32_t idesc, bool acc) {
    uint32_t e = acc ? 1u : 0u;
    asm volatile(
        "{\n\t.reg .pred p;\n\tsetp.ne.u32 p, %5, 0;\n\t"
        "tcgen05.mma.cta_group::2.kind::f16 [%0], %1, %2, %3, "
        "{%4,%4,%4,%4,%4,%4,%4,%4}, p;\n\t}"
        :: "r"(d), "l"(a), "l"(b), "r"(idesc), "r"(0u), "r"(e) : "memory");
}
__device__ __forceinline__ void tc_commit_mc2(uint32_t mbar) {
    asm volatile(
        "tcgen05.commit.cta_group::2.mbarrier::arrive::one.shared::cluster.multicast::cluster.b64 [%0], %1;"
        :: "r"(mbar), "h"((uint16_t)3) : "memory");
}
#define CLUSTER_SYNC() do { \
    asm volatile("barrier.cluster.arrive.aligned;" ::: "memory"); \
    asm volatile("barrier.cluster.wait.aligned;" ::: "memory"); \
} while (0)
#define LDTM_X32(r, ta) \
    asm volatile( \
        "tcgen05.ld.sync.aligned.32x32b.x32.b32 " \
        "{%0,%1,%2,%3,%4,%5,%6,%7,%8,%9,%10,%11,%12,%13,%14,%15," \
        "%16,%17,%18,%19,%20,%21,%22,%23,%24,%25,%26,%27,%28,%29,%30,%31}, [%32];" \
        : "=r"((r)[0]),"=r"((r)[1]),"=r"((r)[2]),"=r"((r)[3]),"=r"((r)[4]),"=r"((r)[5]), \
          "=r"((r)[6]),"=r"((r)[7]),"=r"((r)[8]),"=r"((r)[9]),"=r"((r)[10]),"=r"((r)[11]), \
          "=r"((r)[12]),"=r"((r)[13]),"=r"((r)[14]),"=r"((r)[15]),"=r"((r)[16]),"=r"((r)[17]), \
          "=r"((r)[18]),"=r"((r)[19]),"=r"((r)[20]),"=r"((r)[21]),"=r"((r)[22]),"=r"((r)[23]), \
          "=r"((r)[24]),"=r"((r)[25]),"=r"((r)[26]),"=r"((r)[27]),"=r"((r)[28]),"=r"((r)[29]), \
          "=r"((r)[30]),"=r"((r)[31]) : "r"(ta))
#endif  // HAS_TC

// ---------------- kernel: no-op (ncu capture-slot alignment) ----------------
__global__ void k_nop() {}

// ---------------- kernel: fused prep + embed, role-interleaved ----------------
// First 5056 blocks alternate prep/embed (2528 each); blocks [5056,7136) embed.
// Embed Phase A uses float4 loads over 4 contiguous channels (192 active threads).
#define PREP_BLOCKS (NMEM_PAD/8)      // 2528
__global__ void __launch_bounds__(256) k_pre(const float* __restrict__ f6,
                                             const float* __restrict__ f8,
                                             const float* __restrict__ f10,
                                             const float* __restrict__ mb) {
    extern __shared__ float sP[];     // [768][6]
    int tid = threadIdx.x;
    int bid = blockIdx.x;
    bool is_prep = (bid < 2 * PREP_BLOCKS) && ((bid & 1) == 0);
    int idx = (bid < 2 * PREP_BLOCKS) ? (bid >> 1) : (PREP_BLOCKS + (bid - 2 * PREP_BLOCKS));

    if (is_prep) {
        // ---------------- prep half ----------------
        int warp = tid >> 5, lane = tid & 31;
        int gtid = idx * 256 + tid;
        if (gtid < NPATCH) g_pscores[gtid] = 3.0e38f;

        int row = idx * 8 + warp;
        __nv_bfloat16* dst = g_mb + (size_t)row * KDIM;
        if (row < NMEM) {
            const float4* src = (const float4*)(mb + (size_t)row * KDIM);
            float ss = 0.f;
            #pragma unroll
            for (int j = 0; j < 8; j++) {
                float4 v = src[lane + 32 * j];
                ss += v.x * v.x + v.y * v.y + v.z * v.z + v.w * v.w;
                __nv_bfloat162 h0, h1;
                h0.x = __float2bfloat16(v.x); h0.y = __float2bfloat16(v.y);
                h1.x = __float2bfloat16(v.z); h1.y = __float2bfloat16(v.w);
                uint2 pk; pk.x = *(uint32_t*)&h0; pk.y = *(uint32_t*)&h1;
                *(uint2*)(dst + 4 * (lane + 32 * j)) = pk;
            }
            #pragma unroll
            for (int o = 16; o; o >>= 1) ss += __shfl_xor_sync(0xffffffffu, ss, o);
            if (lane == 0) g_mnorm[row] = ss;
        } else {
            uint2 z; z.x = 0u; z.y = 0u;
            #pragma unroll
            for (int j = 0; j < 8; j++)
                *(uint2*)(dst + 4 * (lane + 32 * j)) = z;
            if (lane == 0) g_mnorm[row] = 1.0e30f;
        }
        return;
    }

    // ---------------- embed half (layer-chunked, float4 Phase A) -------------
    int n  = idx;
    int b  = n / 576;
    int yx = n - b * 576;
    int y  = yx / GRIDW, x = yx - y * GRIDW;

    const size_t pbase = ((size_t)b * 577 + 1 + (size_t)y * GRIDW + x) * CCH;
    bool vy0 = (y > 0), vy2 = (y < GRIDW - 1);
    bool vx0 = (x > 0), vx2 = (x < GRIDW - 1);
    bool vld[9];
    vld[0] = vy0 && vx0; vld[1] = vy0; vld[2] = vy0 && vx2;
    vld[3] = vx0;        vld[4] = true; vld[5] = vx2;
    vld[6] = vy2 && vx0; vld[7] = vy2; vld[8] = vy2 && vx2;
    const int OFF[9] = { (-GRIDW - 1) * CCH, (-GRIDW) * CCH, (-GRIDW + 1) * CCH,
                         -CCH, 0, CCH,
                         (GRIDW - 1) * CCH, GRIDW * CCH, (GRIDW + 1) * CCH };

    float acc[4];
    #pragma unroll
    for (int r = 0; r < 4; r++) acc[r] = 0.f;

    #pragma unroll
    for (int l = 0; l < 3; l++) {
        const float* F = ((l == 0) ? f6 : (l == 1) ? f8 : f10) + pbase;
        // Phase A: 192 threads x 4 contiguous channels, float4 loads.
        if (tid < 192) {
            int c4 = tid * 4;
            float4 v[9];
            #pragma unroll
            for (int pos = 0; pos < 9; pos++) {
                if (vld[pos]) v[pos] = *(const float4*)(F + c4 + OFF[pos]);
                else { v[pos].x = 0.f; v[pos].y = 0.f; v[pos].z = 0.f; v[pos].w = 0.f; }
            }
            #pragma unroll
            for (int k = 0; k < 4; k++) {
                float p0 = (&v[0].x)[k], p1 = (&v[1].x)[k], p2 = (&v[2].x)[k];
                float p3 = (&v[3].x)[k], p4 = (&v[4].x)[k], p5 = (&v[5].x)[k];
                float p6 = (&v[6].x)[k], p7 = (&v[7].x)[k], p8 = (&v[8].x)[k];
                float c2 = p0 + p1;
                float c3 = c2 + p2;
                float c4s = c3 + p3;
                float c5 = c4s + p4;
                float c6 = c5 + p5;
                float c7 = c6 + p6;
                float c9 = c7 + p7 + p8;
                float* o = sP + (c4 + k) * 6;
                o[0] = c7; o[1] = c9 - c6; o[2] = c5;
                o[3] = c9 - c4s; o[4] = c3; o[5] = c9 - c2;
            }
        }
        __syncthreads();
        // Phase B: taps belonging to this layer
        #pragma unroll
        for (int r = 0; r < 4; r++) {
            int i = tid + (r << 8);
            #pragma unroll
            for (int t = 0; t < 3; t++) {
                int j = 3 * i + t;
                if ((j >> 10) == l) {
                    int m = j & 1023;
                    int q = m >> 2, rm = m & 3;
                    int b6 = (3 * q) * 6;
                    int a1 = b6 + ((rm == 0) ? 0 : (rm == 1) ? 1 : (rm == 2) ? 9 : 17);
                    int a2 = b6 + ((rm == 2) ? 16 : 8);
                    bool two = (rm == 1) || (rm == 2);
                    float scale = two ? 0.125f : (1.f / 7.f);
                    float v1 = sP[a1];
                    float v2 = two ? sP[a2] : 0.f;
                    acc[r] += (v1 + v2) * scale;
                }
            }
        }
        __syncthreads();
    }

    float ss = 0.f;
    #pragma unroll
    for (int r = 0; r < 4; r++) {
        float a = acc[r] * (1.f / 3.f);
        g_emb[(size_t)n * KDIM + tid + (r << 8)] = __float2bfloat16(a);
        ss += a * a;
    }
    #pragma unroll
    for (int o = 16; o; o >>= 1) ss += __shfl_xor_sync(0xffffffffu, ss, o);
    __shared__ float sw[8];
    if ((tid & 31) == 0) sw[tid >> 5] = ss;
    __syncthreads();
    if (tid < 8) {
        float v = sw[tid];
        #pragma unroll
        for (int o = 4; o; o >>= 1) v += __shfl_xor_sync(0xffu, v, o);
        if (tid == 0) g_enorm[n] = v;
    }
}

// ============== GEMM path A: tcgen05 cg2 persistent + split-done (R14) =========
__global__ void __launch_bounds__(NTHREADS, 1)
#if HAS_TC
__cluster_dims__(2, 1, 1)
#endif
k_gemm_tc() {
#if HAS_TC
    extern __shared__ __align__(1024) char dsm[];
    uint32_t base = (smem_u32(dsm) + 1023u) & ~1023u;
    int tid  = threadIdx.x;
    int warp = tid >> 5, lane = tid & 31;
    uint32_t rank = ctarank();

    uint32_t bFull  = base + SMEM_BAR;
    uint32_t bEmpty = bFull + 32;
    uint32_t bDone0 = bFull + 64;
    uint32_t bDone1 = bFull + 72;
    uint32_t bFree  = bFull + 80;
    uint32_t tptr   = base + SMEM_TMEMPTR;

    if (tid == 0) {
        for (int s = 0; s < NSTAGE; s++) { mbar_init(bFull + 8*s, 8); mbar_init(bEmpty + 8*s, 1); }
        mbar_init(bDone0, 1);
        mbar_init(bDone1, 1);
        mbar_init(bFree, 512);
    }
    __syncthreads();
    if (warp == 12) {
        asm volatile("tcgen05.alloc.cta_group::2.sync.aligned.shared::cta.b32 [%0], %1;"
                     :: "r"(tptr), "r"(512u) : "memory");
        asm volatile("tcgen05.relinquish_alloc_permit.cta_group::2.sync.aligned;");
    }
    __syncthreads();
    uint32_t tmem;
    asm volatile("ld.shared.b32 %0, [%1];" : "=r"(tmem) : "r"(tptr));

    CLUSTER_SYNC();

    int cidx  = blockIdx.x >> 1;
    int cstep = gridDim.x >> 1;

    if (warp >= 8 && warp < 12) {
        int pt = tid - 256;
        int s = 0, ph = 1;
        int pend0 = -1, pend1 = -1;
        for (int t = cidx; t < NTILES; t += cstep) {
            int mt = t % MT_TILES, nt = t / MT_TILES;
            const __nv_bfloat16* gA0 = g_emb + (size_t)(mt * TILE_M + rank * 128) * KDIM;
            const __nv_bfloat16* gA1 = gA0 + (size_t)256 * KDIM;
            const __nv_bfloat16* gB  = g_mb + (size_t)(nt * TILE_N + rank * 128) * KDIM;
            for (int kc = 0; kc < KCHUNKS; kc++) {
                mbar_wait(bEmpty + 8*s, ph);
                int k0 = kc * TILE_K;
                uint32_t st = base + s * STAGE_BYTES;
                #pragma unroll
                for (int i = 0; i < 24; i++) {
                    int c = pt + 128 * i;
                    int r = (c & 1023) >> 3, seg = c & 7;
                    uint32_t soff = SW128X(r * 128 + seg * 16);
                    const __nv_bfloat16* src;
                    uint32_t dst;
                    if (c < 1024)      { src = gA0 + (size_t)r * KDIM + k0 + seg * 8; dst = st + soff; }
                    else if (c < 2048) { src = gA1 + (size_t)r * KDIM + k0 + seg * 8; dst = st + A_HALF + soff; }
                    else               { src = gB  + (size_t)r * KDIM + k0 + seg * 8; dst = st + 2*A_HALF + soff; }
                    cp16(dst, src);
                }
                asm volatile("cp.async.commit_group;");
                if (pend0 >= 0) {
                    asm volatile("cp.async.wait_group 2;");
                    asm volatile("fence.proxy.async.shared::cta;" ::: "memory");
                    __syncwarp();
                    if (lane == 0) mbar_arrive_rank0(bFull + 8*pend0);
                }
                pend0 = pend1; pend1 = s;
                if (++s == NSTAGE) { s = 0; ph ^= 1; }
            }
        }
        if (pend0 >= 0) {
            asm volatile("cp.async.wait_group 1;");
            asm volatile("fence.proxy.async.shared::cta;" ::: "memory");
            __syncwarp();
            if (lane == 0) mbar_arrive_rank0(bFull + 8*pend0);
        }
        if (pend1 >= 0) {
            asm volatile("cp.async.wait_group 0;");
            asm volatile("fence.proxy.async.shared::cta;" ::: "memory");
            __syncwarp();
            if (lane == 0) mbar_arrive_rank0(bFull + 8*pend1);
        }
    } else if (warp == 12) {
        if (rank == 0) {
            int s = 0, ph = 0;
            int phFree = 1;
            for (int t = cidx; t < NTILES; t += cstep) {
                mbar_wait(bFree, phFree); phFree ^= 1;
                asm volatile("tcgen05.fence::after_thread_sync;" ::: "memory");
                for (int kc = 0; kc < KCHUNKS; kc++) {
                    mbar_wait(bFull + 8*s, ph);
                    if (elect1()) {
                        uint32_t st = base + s * STAGE_BYTES;
                        uint64_t ad0 = mk_desc_sw128(st);
                        uint64_t ad1 = mk_desc_sw128(st + A_HALF);
                        uint64_t bd  = mk_desc_sw128(st + 2*A_HALF);
                        if (kc == KCHUNKS - 1) {
                            #pragma unroll
                            for (int k4 = 0; k4 < 4; k4++)
                                mma_f16_ss_cg2(tmem,       ad0 + 2*k4, bd + 2*k4, GEMM_IDESC, true);
                            tc_commit_mc2(bDone0);
                            #pragma unroll
                            for (int k4 = 0; k4 < 4; k4++)
                                mma_f16_ss_cg2(tmem + 256, ad1 + 2*k4, bd + 2*k4, GEMM_IDESC, true);
                            tc_commit_mc2(bEmpty + 8*s);
                            tc_commit_mc2(bDone1);
                        } else {
                            #pragma unroll
                            for (int k4 = 0; k4 < 4; k4++) {
                                mma_f16_ss_cg2(tmem,       ad0 + 2*k4, bd + 2*k4, GEMM_IDESC, (kc | k4) != 0);
                                mma_f16_ss_cg2(tmem + 256, ad1 + 2*k4, bd + 2*k4, GEMM_IDESC, (kc | k4) != 0);
                            }
                            tc_commit_mc2(bEmpty + 8*s);
                        }
                    }
                    if (++s == NSTAGE) { s = 0; ph ^= 1; }
                }
            }
        }
    } else {
        int phDone = 0;
        int half = warp >> 2;
        uint32_t bMy = (half == 0) ? bDone0 : bDone1;
        uint32_t dtm = tmem + half * TILE_N;
        int lt = 0;
        for (int t = cidx; t < NTILES; t += cstep, lt++) {
            int mt = t % MT_TILES, nt = t / MT_TILES;
            uint32_t smn = base + SMEM_MNORM + (lt & 1) * 1024;
            {
                float v = g_mnorm[nt * TILE_N + tid];
                asm volatile("st.shared.f32 [%0], %1;" :: "r"(smn + 4u*tid), "f"(v) : "memory");
            }
            asm volatile("bar.sync 1, 256;" ::: "memory");
            mbar_wait(bMy, phDone); phDone ^= 1;
            asm volatile("tcgen05.fence::after_thread_sync;" ::: "memory");

            float vmin = 3e38f;
            #pragma unroll
            for (int c0 = 0; c0 < TILE_N; c0 += 64) {
                uint32_t r0[32], r1[32];
                LDTM_X32(r0, dtm + c0);
                LDTM_X32(r1, dtm + c0 + 32);
                asm volatile("tcgen05.wait::ld.sync.aligned;" ::: "memory");
                #pragma unroll
                for (int j = 0; j < 32; j++) {
                    float mn0, mn1;
                    asm volatile("ld.shared.f32 %0, [%1];" : "=f"(mn0) : "r"(smn + 4u*(c0 + j)));
                    asm volatile("ld.shared.f32 %0, [%1];" : "=f"(mn1) : "r"(smn + 4u*(c0 + 32 + j)));
                    vmin = fminf(vmin, fmaf(-2.f, __uint_as_float(r0[j]), mn0));
                    vmin = fminf(vmin, fmaf(-2.f, __uint_as_float(r1[j]), mn1));
                }
            }
            asm volatile("tcgen05.fence::before_thread_sync;" ::: "memory");
            mbar_arrive_rank0(bFree);

            int m = mt * TILE_M + half * 256 + (int)rank * 128 + (warp & 3) * 32 + lane;
            float v = g_enorm[m] + vmin;
            atomicMin((int*)&g_pscores[m], __float_as_int(v));
        }
    }

    __syncthreads();
    CLUSTER_SYNC();
    if (warp == 12) {
        asm volatile("tcgen05.dealloc.cta_group::2.sync.aligned.b32 %0, %1;"
                     :: "r"(tmem), "r"(512u));
    }
    CLUSTER_SYNC();
#endif  // HAS_TC
}

// ================= GEMM path B: mma.sync fallback (base-arch image) ============
#define KTILE   32
#define ASTRIDE 40

__global__ void __launch_bounds__(256) k_gemm_fb() {
#if !HAS_TC
    __shared__ __align__(16) __nv_bfloat16 As[2][128 * ASTRIDE];
    __shared__ __align__(16) __nv_bfloat16 Bs[2][128 * ASTRIDE];
    __shared__ float sRed[2][128];

    int ntile = blockIdx.x, mtile = blockIdx.y;
    int tid = threadIdx.x;
    int warp = tid >> 5, lane = tid & 31;
    int wm = warp >> 1, wn = warp & 1;
    int g = lane >> 2, T = lane & 3;

    const __nv_bfloat16* gA = g_emb + (size_t)(mtile * 128) * KDIM;
    const __nv_bfloat16* gB = g_mb  + (size_t)(ntile * 128) * KDIM;

    float acc[2][8][4];
    #pragma unroll
    for (int a = 0; a < 2; a++)
        #pragma unroll
        for (int b = 0; b < 8; b++)
            #pragma unroll
            for (int c = 0; c < 4; c++) acc[a][b][c] = 0.f;

    auto issue = [&](int stage, int kc) {
        int k0 = kc * KTILE;
        #pragma unroll
        for (int it = 0; it < 2; it++) {
            int ci = tid + it * 256;
            int row = ci >> 2, seg = ci & 3;
            cp16((uint32_t)__cvta_generic_to_shared(&As[stage][row * ASTRIDE + seg * 8]),
                 gA + (size_t)row * KDIM + k0 + seg * 8);
            cp16((uint32_t)__cvta_generic_to_shared(&Bs[stage][row * ASTRIDE + seg * 8]),
                 gB + (size_t)row * KDIM + k0 + seg * 8);
        }
        asm volatile("cp.async.commit_group;\n");
    };

    issue(0, 0);
    for (int kc = 0; kc < KDIM / KTILE; kc++) {
        int cur = kc & 1;
        if (kc + 1 < KDIM / KTILE) {
            issue(cur ^ 1, kc + 1);
            asm volatile("cp.async.wait_group 1;\n");
        } else {
            asm volatile("cp.async.wait_group 0;\n");
        }
        __syncthreads();

        #pragma unroll
        for (int ks = 0; ks < 2; ks++) {
            int kk = ks * 16;
            uint32_t afr[2][4], bfr[8][2];
            #pragma unroll
            for (int mt = 0; mt < 2; mt++) {
                int r0 = wm * 32 + mt * 16 + g;
                const __nv_bfloat16* basep = &As[cur][0];
                afr[mt][0] = *(const uint32_t*)&basep[(r0)     * ASTRIDE + kk + 2 * T];
                afr[mt][1] = *(const uint32_t*)&basep[(r0 + 8) * ASTRIDE + kk + 2 * T];
                afr[mt][2] = *(const uint32_t*)&basep[(r0)     * ASTRIDE + kk + 2 * T + 8];
                afr[mt][3] = *(const uint32_t*)&basep[(r0 + 8) * ASTRIDE + kk + 2 * T + 8];
            }
            #pragma unroll
            for (int nt = 0; nt < 8; nt++) {
                int c0 = wn * 64 + nt * 8 + g;
                const __nv_bfloat16* basep = &Bs[cur][0];
                bfr[nt][0] = *(const uint32_t*)&basep[c0 * ASTRIDE + kk + 2 * T];
                bfr[nt][1] = *(const uint32_t*)&basep[c0 * ASTRIDE + kk + 2 * T + 8];
            }
            #pragma unroll
            for (int mt = 0; mt < 2; mt++)
                #pragma unroll
                for (int nt = 0; nt < 8; nt++) {
                    asm volatile(
                        "mma.sync.aligned.m16n8k16.row.col.f32.bf16.bf16.f32 "
                        "{%0,%1,%2,%3}, {%4,%5,%6,%7}, {%8,%9}, {%0,%1,%2,%3};\n"
                        : "+f"(acc[mt][nt][0]), "+f"(acc[mt][nt][1]),
                          "+f"(acc[mt][nt][2]), "+f"(acc[mt][nt][3])
                        : "r"(afr[mt][0]), "r"(afr[mt][1]), "r"(afr[mt][2]), "r"(afr[mt][3]),
                          "r"(bfr[nt][0]), "r"(bfr[nt][1]));
                }
        }
        __syncthreads();
    }

    float rmin[2][2];
    #pragma unroll
    for (int mt = 0; mt < 2; mt++) { rmin[mt][0] = 3e38f; rmin[mt][1] = 3e38f; }
    #pragma unroll
    for (int nt = 0; nt < 8; nt++) {
        int cg = ntile * 128 + wn * 64 + nt * 8 + 2 * T;
        float mn0 = g_mnorm[cg];
        float mn1 = g_mnorm[cg + 1];
        #pragma unroll
        for (int mt = 0; mt < 2; mt++) {
            rmin[mt][0] = fminf(rmin[mt][0],
                           fminf(mn0 - 2.f * acc[mt][nt][0], mn1 - 2.f * acc[mt][nt][1]));
            rmin[mt][1] = fminf(rmin[mt][1],
                           fminf(mn0 - 2.f * acc[mt][nt][2], mn1 - 2.f * acc[mt][nt][3]));
        }
    }
    #pragma unroll
    for (int mt = 0; mt < 2; mt++)
        #pragma unroll
        for (int h = 0; h < 2; h++) {
            float v = rmin[mt][h];
            v = fminf(v, __shfl_xor_sync(0xffffffffu, v, 1));
            v = fminf(v, __shfl_xor_sync(0xffffffffu, v, 2));
            rmin[mt][h] = v;
        }
    if (T == 0) {
        #pragma unroll
        for (int mt = 0; mt < 2; mt++) {
            sRed[wn][wm * 32 + mt * 16 + g]     = rmin[mt][0];
            sRed[wn][wm * 32 + mt * 16 + g + 8] = rmin[mt][1];
        }
    }
    __syncthreads();
    if (tid < 128) {
        float v = fminf(sRed[0][tid], sRed[1][tid]);
        int grow = mtile * 128 + tid;
        v += g_enorm[grow];
        atomicMin((int*)&g_pscores[grow], __float_as_int(v));
    }
#endif  // !HAS_TC
}

// ---------------- kernel: fused image scores + float4 bilinear masks ----------
__global__ void __launch_bounds__(256) k_tail(float* __restrict__ out) {
    if (blockIdx.x >= 1152) {
        int b = blockIdx.x - 1152;
        int tid = threadIdx.x;
        float m = -3e38f;
        for (int i = tid; i < 576; i += 256) m = fmaxf(m, g_pscores[b * 576 + i]);
        __shared__ float sred[256];
        sred[tid] = m; __syncthreads();
        for (int s = 128; s > 0; s >>= 1) { if (tid < s) sred[tid] = fmaxf(sred[tid], sred[tid + s]); __syncthreads(); }
        if (tid == 0) out[b] = sred[0];
        return;
    }
    int q = blockIdx.x * 256 + threadIdx.x;
    int elem = q * 4;
    int b = elem / (IMG * IMG);
    int r = elem - b * (IMG * IMG);
    int oy = r / IMG, ox = r - oy * IMG;

    float ys = (oy + 0.5f) * (1.f / 16.f) - 0.5f;
    float yf = floorf(ys);
    float wy = ys - yf;
    int y0 = max(0, min(GRIDW - 1, (int)yf));
    int y1 = max(0, min(GRIDW - 1, (int)yf + 1));
    const float* ps = g_pscores + b * 576;
    const float* r0p = ps + y0 * GRIDW;
    const float* r1p = ps + y1 * GRIDW;

    float4 res;
    float* rp = (float*)&res;
    #pragma unroll
    for (int k = 0; k < 4; k++) {
        float xs = (ox + k + 0.5f) * (1.f / 16.f) - 0.5f;
        float xf = floorf(xs);
        float wx = xs - xf;
        int x0 = max(0, min(GRIDW - 1, (int)xf));
        int x1 = max(0, min(GRIDW - 1, (int)xf + 1));
        float v00 = r0p[x0], v01 = r0p[x1];
        float v10 = r1p[x0], v11 = r1p[x1];
        rp[k] = (1.f - wy) * ((1.f - wx) * v00 + wx * v01)
              +        wy  * ((1.f - wx) * v10 + wx * v11);
    }
    *(float4*)(out + BATCH + elem) = res;
}

// ---------------- launch ----------------
extern "C" void kernel_launch(void* const* d_in, const int* in_sizes, int n_in,
                              void* d_out, int out_size) {
    const float* f6  = (const float*)d_in[0];
    const float* f8  = (const float*)d_in[1];
    const float* f10 = (const float*)d_in[2];
    const float* mb  = (const float*)d_in[3];
    float* out = (float*)d_out;

    int nsm = 148;
    cudaDeviceGetAttribute(&nsm, cudaDevAttrMultiProcessorCount, 0);
    nsm &= ~1;

    cudaFuncSetAttribute(k_pre,     cudaFuncAttributeMaxDynamicSharedMemorySize, EMB_SMEM);
    cudaFuncSetAttribute(k_gemm_tc, cudaFuncAttributeMaxDynamicSharedMemorySize, SMEM_DYN);

    // k_pre is the 2nd launch; k_gemm_tc the 4th (ncu capture window).
    k_nop<<<1, 1>>>();
    k_pre<<<PREP_BLOCKS + NPATCH, 256, EMB_SMEM>>>(f6, f8, f10, mb);
    k_gemm_fb<<<dim3(NMEM_PAD / 128, NPATCH / 128), 256>>>();
    k_gemm_tc<<<nsm, NTHREADS, SMEM_DYN>>>();
    k_tail<<<1160, 256>>>(out);
}

// round 16
// speedup vs baseline: 1.0530x; 1.0530x over previous
#include <cuda_runtime.h>
#include <cuda_bf16.h>
#include <cstdint>

// ---- feature gate: tcgen05 only exists in arch-accelerated / family passes ----
#if defined(__CUDA_ARCH__) && (defined(__CUDA_ARCH_FEAT_SM103_ALL) || \
                               defined(__CUDA_ARCH_FEAT_SM100_ALL) || \
                               defined(__CUDA_ARCH_FEAT_SM101_ALL) || \
                               (defined(__CUDA_ARCH_FAMILY_SPECIFIC__) && \
                                (__CUDA_ARCH_FAMILY_SPECIFIC__ == 1000 || \
                                 __CUDA_ARCH_FAMILY_SPECIFIC__ == 1010 || \
                                 __CUDA_ARCH_FAMILY_SPECIFIC__ == 1030)))
#define HAS_TC 1
#else
#define HAS_TC 0
#endif

// ---------------- problem constants ----------------
#define BATCH   8
#define GRIDW   24
#define CCH     768
#define NPATCH  (BATCH*GRIDW*GRIDW)   // 4608
#define KDIM    1024
#define NMEM    20000
#define NMEM_PAD 20224                // 79*256
#define IMG     384

// ---------------- cg2 GEMM tiling: cluster tile M=512 x N=256 ----------------
#define TILE_M   512
#define TILE_N   256
#define TILE_K   64
#define NSTAGE   4
#define MT_TILES (NPATCH/TILE_M)      // 9
#define NT_TILES (NMEM_PAD/TILE_N)    // 79
#define NTILES   (MT_TILES*NT_TILES)  // 711
#define KCHUNKS  (KDIM/TILE_K)        // 16

#define A_HALF      16384
#define STAGE_BYTES (3*A_HALF)        // 49152

#define NTHREADS 416                  // 8 epi + 4 producer + 1 mma warps

#define SMEM_MNORM   (NSTAGE*STAGE_BYTES)      // 196608, 2KB (lt-parity buffers)
#define SMEM_BAR     (SMEM_MNORM + 2048)
#define SMEM_TMEMPTR (SMEM_BAR + 96)
#define SMEM_DYN     (SMEM_TMEMPTR + 16 + 1024)

#define GEMM_IDESC ((1u<<4)|(1u<<7)|(1u<<10)|((TILE_N/8u)<<17)|((256u/16u)<<24))

// embed smem: one layer's [768][6] floats (layer-chunked)
#define EMB_SMEM (768*6*4)            // 18432

// ---------------- scratch ----------------
__device__ __nv_bfloat16 g_mb[(size_t)NMEM_PAD * KDIM];
__device__ float         g_mnorm[NMEM_PAD];
__device__ __nv_bfloat16 g_emb[(size_t)NPATCH * KDIM];
__device__ float         g_enorm[NPATCH];
__device__ float         g_pscores[NPATCH];

// ---------------- common helpers ----------------
__device__ __forceinline__ uint32_t smem_u32(const void* p) {
    uint32_t a;
    asm("{ .reg .u64 t; cvta.to.shared.u64 t, %1; cvt.u32.u64 %0, t; }" : "=r"(a) : "l"(p));
    return a;
}
__device__ __forceinline__ void cp16(uint32_t dst, const void* src) {
    asm volatile("cp.async.cg.shared.global [%0], [%1], 16;" :: "r"(dst), "l"(src));
}
#define SW128X(o) ((o) ^ (((o) >> 3) & 0x70))

#if HAS_TC
__device__ __forceinline__ void mbar_init(uint32_t a, uint32_t c) {
    asm volatile("mbarrier.init.shared.b64 [%0], %1;" :: "r"(a), "r"(c) : "memory");
}
__device__ __forceinline__ void mbar_arrive_rank0(uint32_t a) {
    asm volatile(
        "{\n\t.reg .b32 rem;\n\t"
        "mapa.shared::cluster.u32 rem, %0, 0;\n\t"
        "mbarrier.arrive.shared::cluster.b64 _, [rem];\n\t}"
        :: "r"(a) : "memory");
}
__device__ __forceinline__ void mbar_wait(uint32_t a, uint32_t parity) {
    asm volatile(
        "{\n\t.reg .pred P;\n"
        "WL_%=:\n\t"
        "mbarrier.try_wait.parity.acquire.cta.shared::cta.b64 P, [%0], %1, 0x989680;\n\t"
        "@P bra.uni WD_%=;\n\t"
        "bra.uni WL_%=;\n"
        "WD_%=:\n\t}"
        :: "r"(a), "r"(parity) : "memory");
}
__device__ __forceinline__ bool elect1() {
    uint32_t p;
    asm volatile("{\n\t.reg .pred P;\n\telect.sync _|P, 0xFFFFFFFF;\n\tselp.b32 %0,1,0,P;\n\t}" : "=r"(p));
    return p != 0;
}
__device__ __forceinline__ uint32_t ctarank() {
    uint32_t r; asm("mov.u32 %0, %%cluster_ctarank;" : "=r"(r)); return r;
}
__device__ __forceinline__ uint64_t mk_desc_sw128(uint32_t addr) {
    return ((uint64_t)2 << 61) | ((uint64_t)1 << 46) | ((uint64_t)64 << 32) |
           ((uint64_t)1 << 16) | (((uint64_t)addr >> 4) & 0x3FFF);
}
__device__ __forceinline__ void mma_f16_ss_cg2(uint32_t d, uint64_t a, uint64_t b,
                                               uint32_t idesc, bool acc) {
    uint32_t e = acc ? 1u : 0u;
    asm volatile(
        "{\n\t.reg .pred p;\n\tsetp.ne.u32 p, %5, 0;\n\t"
        "tcgen05.mma.cta_group::2.kind::f16 [%0], %1, %2, %3, "
        "{%4,%4,%4,%4,%4,%4,%4,%4}, p;\n\t}"
        :: "r"(d), "l"(a), "l"(b), "r"(idesc), "r"(0u), "r"(e) : "memory");
}
__device__ __forceinline__ void tc_commit_mc2(uint32_t mbar) {
    asm volatile(
        "tcgen05.commit.cta_group::2.mbarrier::arrive::one.shared::cluster.multicast::cluster.b64 [%0], %1;"
        :: "r"(mbar), "h"((uint16_t)3) : "memory");
}
#define CLUSTER_SYNC() do { \
    asm volatile("barrier.cluster.arrive.aligned;" ::: "memory"); \
    asm volatile("barrier.cluster.wait.aligned;" ::: "memory"); \
} while (0)
#define LDTM_X32(r, ta) \
    asm volatile( \
        "tcgen05.ld.sync.aligned.32x32b.x32.b32 " \
        "{%0,%1,%2,%3,%4,%5,%6,%7,%8,%9,%10,%11,%12,%13,%14,%15," \
        "%16,%17,%18,%19,%20,%21,%22,%23,%24,%25,%26,%27,%28,%29,%30,%31}, [%32];" \
        : "=r"((r)[0]),"=r"((r)[1]),"=r"((r)[2]),"=r"((r)[3]),"=r"((r)[4]),"=r"((r)[5]), \
          "=r"((r)[6]),"=r"((r)[7]),"=r"((r)[8]),"=r"((r)[9]),"=r"((r)[10]),"=r"((r)[11]), \
          "=r"((r)[12]),"=r"((r)[13]),"=r"((r)[14]),"=r"((r)[15]),"=r"((r)[16]),"=r"((r)[17]), \
          "=r"((r)[18]),"=r"((r)[19]),"=r"((r)[20]),"=r"((r)[21]),"=r"((r)[22]),"=r"((r)[23]), \
          "=r"((r)[24]),"=r"((r)[25]),"=r"((r)[26]),"=r"((r)[27]),"=r"((r)[28]),"=r"((r)[29]), \
          "=r"((r)[30]),"=r"((r)[31]) : "r"(ta))
#endif  // HAS_TC

// ---------------- kernel: no-op (ncu capture-slot alignment) ----------------
__global__ void k_nop() {}

// ---------------- kernel: fused prep + embed, role-interleaved (R14 base) -----
// First 5056 blocks alternate prep/embed (2528 each); blocks [5056,7136) embed.
// Phase B prunes the r-loop per layer: taps of layer l only live in r in {l, l+1}.
#define PREP_BLOCKS (NMEM_PAD/8)      // 2528
__global__ void __launch_bounds__(256) k_pre(const float* __restrict__ f6,
                                             const float* __restrict__ f8,
                                             const float* __restrict__ f10,
                                             const float* __restrict__ mb) {
    extern __shared__ float sP[];     // [768][6]
    int tid = threadIdx.x;
    int bid = blockIdx.x;
    bool is_prep = (bid < 2 * PREP_BLOCKS) && ((bid & 1) == 0);
    int idx = (bid < 2 * PREP_BLOCKS) ? (bid >> 1) : (PREP_BLOCKS + (bid - 2 * PREP_BLOCKS));

    if (is_prep) {
        // ---------------- prep half ----------------
        int warp = tid >> 5, lane = tid & 31;
        int gtid = idx * 256 + tid;
        if (gtid < NPATCH) g_pscores[gtid] = 3.0e38f;

        int row = idx * 8 + warp;
        __nv_bfloat16* dst = g_mb + (size_t)row * KDIM;
        if (row < NMEM) {
            const float4* src = (const float4*)(mb + (size_t)row * KDIM);
            float ss = 0.f;
            #pragma unroll
            for (int j = 0; j < 8; j++) {
                float4 v = src[lane + 32 * j];
                ss += v.x * v.x + v.y * v.y + v.z * v.z + v.w * v.w;
                __nv_bfloat162 h0, h1;
                h0.x = __float2bfloat16(v.x); h0.y = __float2bfloat16(v.y);
                h1.x = __float2bfloat16(v.z); h1.y = __float2bfloat16(v.w);
                uint2 pk; pk.x = *(uint32_t*)&h0; pk.y = *(uint32_t*)&h1;
                *(uint2*)(dst + 4 * (lane + 32 * j)) = pk;
            }
            #pragma unroll
            for (int o = 16; o; o >>= 1) ss += __shfl_xor_sync(0xffffffffu, ss, o);
            if (lane == 0) g_mnorm[row] = ss;
        } else {
            uint2 z; z.x = 0u; z.y = 0u;
            #pragma unroll
            for (int j = 0; j < 8; j++)
                *(uint2*)(dst + 4 * (lane + 32 * j)) = z;
            if (lane == 0) g_mnorm[row] = 1.0e30f;
        }
        return;
    }

    // ---------------- embed half (layer-chunked, scalar Phase A — R14) -------
    int n  = idx;
    int b  = n / 576;
    int yx = n - b * 576;
    int y  = yx / GRIDW, x = yx - y * GRIDW;

    const size_t pbase = ((size_t)b * 577 + 1 + (size_t)y * GRIDW + x) * CCH;
    bool vy0 = (y > 0), vy2 = (y < GRIDW - 1);
    bool vx0 = (x > 0), vx2 = (x < GRIDW - 1);
    bool vld[9];
    vld[0] = vy0 && vx0; vld[1] = vy0; vld[2] = vy0 && vx2;
    vld[3] = vx0;        vld[4] = true; vld[5] = vx2;
    vld[6] = vy2 && vx0; vld[7] = vy2; vld[8] = vy2 && vx2;
    const int OFF[9] = { (-GRIDW - 1) * CCH, (-GRIDW) * CCH, (-GRIDW + 1) * CCH,
                         -CCH, 0, CCH,
                         (GRIDW - 1) * CCH, GRIDW * CCH, (GRIDW + 1) * CCH };

    float acc[4];
    #pragma unroll
    for (int r = 0; r < 4; r++) acc[r] = 0.f;

    #pragma unroll
    for (int l = 0; l < 3; l++) {
        const float* F = ((l == 0) ? f6 : (l == 1) ? f8 : f10) + pbase;
        // Phase A: prefix combinations for this layer's 768 channels (scalar)
        #pragma unroll
        for (int it = 0; it < 3; it++) {
            int c = tid + it * 256;
            float v[9];
            #pragma unroll
            for (int pos = 0; pos < 9; pos++) v[pos] = vld[pos] ? F[c + OFF[pos]] : 0.f;
            float c2 = v[0] + v[1];
            float c3 = c2 + v[2];
            float c4 = c3 + v[3];
            float c5 = c4 + v[4];
            float c6 = c5 + v[5];
            float c7 = c6 + v[6];
            float c9 = c7 + v[7] + v[8];
            float* o = sP + c * 6;
            o[0] = c7; o[1] = c9 - c6; o[2] = c5;
            o[3] = c9 - c4; o[4] = c3; o[5] = c9 - c2;
        }
        __syncthreads();
        // Phase B: only r in {l, l+1} can contain taps of layer l
        #pragma unroll
        for (int rr = 0; rr < 2; rr++) {
            int r = l + rr;                  // compile-time per (l, rr)
            int i = tid + (r << 8);
            #pragma unroll
            for (int t = 0; t < 3; t++) {
                int j = 3 * i + t;
                if ((j >> 10) == l) {
                    int m = j & 1023;
                    int q = m >> 2, rm = m & 3;
                    int b6 = (3 * q) * 6;
                    int a1 = b6 + ((rm == 0) ? 0 : (rm == 1) ? 1 : (rm == 2) ? 9 : 17);
                    int a2 = b6 + ((rm == 2) ? 16 : 8);
                    bool two = (rm == 1) || (rm == 2);
                    float scale = two ? 0.125f : (1.f / 7.f);
                    float v1 = sP[a1];
                    float v2 = two ? sP[a2] : 0.f;
                    acc[r] += (v1 + v2) * scale;
                }
            }
        }
        __syncthreads();
    }

    float ss = 0.f;
    #pragma unroll
    for (int r = 0; r < 4; r++) {
        float a = acc[r] * (1.f / 3.f);
        g_emb[(size_t)n * KDIM + tid + (r << 8)] = __float2bfloat16(a);
        ss += a * a;
    }
    #pragma unroll
    for (int o = 16; o; o >>= 1) ss += __shfl_xor_sync(0xffffffffu, ss, o);
    __shared__ float sw[8];
    if ((tid & 31) == 0) sw[tid >> 5] = ss;
    __syncthreads();
    if (tid < 8) {
        float v = sw[tid];
        #pragma unroll
        for (int o = 4; o; o >>= 1) v += __shfl_xor_sync(0xffu, v, o);
        if (tid == 0) g_enorm[n] = v;
    }
}

// ============== GEMM path A: tcgen05 cg2 persistent + split-done (R14) =========
__global__ void __launch_bounds__(NTHREADS, 1)
#if HAS_TC
__cluster_dims__(2, 1, 1)
#endif
k_gemm_tc() {
#if HAS_TC
    extern __shared__ __align__(1024) char dsm[];
    uint32_t base = (smem_u32(dsm) + 1023u) & ~1023u;
    int tid  = threadIdx.x;
    int warp = tid >> 5, lane = tid & 31;
    uint32_t rank = ctarank();

    uint32_t bFull  = base + SMEM_BAR;
    uint32_t bEmpty = bFull + 32;
    uint32_t bDone0 = bFull + 64;
    uint32_t bDone1 = bFull + 72;
    uint32_t bFree  = bFull + 80;
    uint32_t tptr   = base + SMEM_TMEMPTR;

    if (tid == 0) {
        for (int s = 0; s < NSTAGE; s++) { mbar_init(bFull + 8*s, 8); mbar_init(bEmpty + 8*s, 1); }
        mbar_init(bDone0, 1);
        mbar_init(bDone1, 1);
        mbar_init(bFree, 512);
    }
    __syncthreads();
    if (warp == 12) {
        asm volatile("tcgen05.alloc.cta_group::2.sync.aligned.shared::cta.b32 [%0], %1;"
                     :: "r"(tptr), "r"(512u) : "memory");
        asm volatile("tcgen05.relinquish_alloc_permit.cta_group::2.sync.aligned;");
    }
    __syncthreads();
    uint32_t tmem;
    asm volatile("ld.shared.b32 %0, [%1];" : "=r"(tmem) : "r"(tptr));

    CLUSTER_SYNC();

    int cidx  = blockIdx.x >> 1;
    int cstep = gridDim.x >> 1;

    if (warp >= 8 && warp < 12) {
        int pt = tid - 256;
        int s = 0, ph = 1;
        int pend0 = -1, pend1 = -1;
        for (int t = cidx; t < NTILES; t += cstep) {
            int mt = t % MT_TILES, nt = t / MT_TILES;
            const __nv_bfloat16* gA0 = g_emb + (size_t)(mt * TILE_M + rank * 128) * KDIM;
            const __nv_bfloat16* gA1 = gA0 + (size_t)256 * KDIM;
            const __nv_bfloat16* gB  = g_mb + (size_t)(nt * TILE_N + rank * 128) * KDIM;
            for (int kc = 0; kc < KCHUNKS; kc++) {
                mbar_wait(bEmpty + 8*s, ph);
                int k0 = kc * TILE_K;
                uint32_t st = base + s * STAGE_BYTES;
                #pragma unroll
                for (int i = 0; i < 24; i++) {
                    int c = pt + 128 * i;
                    int r = (c & 1023) >> 3, seg = c & 7;
                    uint32_t soff = SW128X(r * 128 + seg * 16);
                    const __nv_bfloat16* src;
                    uint32_t dst;
                    if (c < 1024)      { src = gA0 + (size_t)r * KDIM + k0 + seg * 8; dst = st + soff; }
                    else if (c < 2048) { src = gA1 + (size_t)r * KDIM + k0 + seg * 8; dst = st + A_HALF + soff; }
                    else               { src = gB  + (size_t)r * KDIM + k0 + seg * 8; dst = st + 2*A_HALF + soff; }
                    cp16(dst, src);
                }
                asm volatile("cp.async.commit_group;");
                if (pend0 >= 0) {
                    asm volatile("cp.async.wait_group 2;");
                    asm volatile("fence.proxy.async.shared::cta;" ::: "memory");
                    __syncwarp();
                    if (lane == 0) mbar_arrive_rank0(bFull + 8*pend0);
                }
                pend0 = pend1; pend1 = s;
                if (++s == NSTAGE) { s = 0; ph ^= 1; }
            }
        }
        if (pend0 >= 0) {
            asm volatile("cp.async.wait_group 1;");
            asm volatile("fence.proxy.async.shared::cta;" ::: "memory");
            __syncwarp();
            if (lane == 0) mbar_arrive_rank0(bFull + 8*pend0);
        }
        if (pend1 >= 0) {
            asm volatile("cp.async.wait_group 0;");
            asm volatile("fence.proxy.async.shared::cta;" ::: "memory");
            __syncwarp();
            if (lane == 0) mbar_arrive_rank0(bFull + 8*pend1);
        }
    } else if (warp == 12) {
        if (rank == 0) {
            int s = 0, ph = 0;
            int phFree = 1;
            for (int t = cidx; t < NTILES; t += cstep) {
                mbar_wait(bFree, phFree); phFree ^= 1;
                asm volatile("tcgen05.fence::after_thread_sync;" ::: "memory");
                for (int kc = 0; kc < KCHUNKS; kc++) {
                    mbar_wait(bFull + 8*s, ph);
                    if (elect1()) {
                        uint32_t st = base + s * STAGE_BYTES;
                        uint64_t ad0 = mk_desc_sw128(st);
                        uint64_t ad1 = mk_desc_sw128(st + A_HALF);
                        uint64_t bd  = mk_desc_sw128(st + 2*A_HALF);
                        if (kc == KCHUNKS - 1) {
                            #pragma unroll
                            for (int k4 = 0; k4 < 4; k4++)
                                mma_f16_ss_cg2(tmem,       ad0 + 2*k4, bd + 2*k4, GEMM_IDESC, true);
                            tc_commit_mc2(bDone0);
                            #pragma unroll
                            for (int k4 = 0; k4 < 4; k4++)
                                mma_f16_ss_cg2(tmem + 256, ad1 + 2*k4, bd + 2*k4, GEMM_IDESC, true);
                            tc_commit_mc2(bEmpty + 8*s);
                            tc_commit_mc2(bDone1);
                        } else {
                            #pragma unroll
                            for (int k4 = 0; k4 < 4; k4++) {
                                mma_f16_ss_cg2(tmem,       ad0 + 2*k4, bd + 2*k4, GEMM_IDESC, (kc | k4) != 0);
                                mma_f16_ss_cg2(tmem + 256, ad1 + 2*k4, bd + 2*k4, GEMM_IDESC, (kc | k4) != 0);
                            }
                            tc_commit_mc2(bEmpty + 8*s);
                        }
                    }
                    if (++s == NSTAGE) { s = 0; ph ^= 1; }
                }
            }
        }
    } else {
        int phDone = 0;
        int half = warp >> 2;
        uint32_t bMy = (half == 0) ? bDone0 : bDone1;
        uint32_t dtm = tmem + half * TILE_N;
        int lt = 0;
        for (int t = cidx; t < NTILES; t += cstep, lt++) {
            int mt = t % MT_TILES, nt = t / MT_TILES;
            uint32_t smn = base + SMEM_MNORM + (lt & 1) * 1024;
            {
                float v = g_mnorm[nt * TILE_N + tid];
                asm volatile("st.shared.f32 [%0], %1;" :: "r"(smn + 4u*tid), "f"(v) : "memory");
            }
            asm volatile("bar.sync 1, 256;" ::: "memory");
            mbar_wait(bMy, phDone); phDone ^= 1;
            asm volatile("tcgen05.fence::after_thread_sync;" ::: "memory");

            float vmin = 3e38f;
            #pragma unroll
            for (int c0 = 0; c0 < TILE_N; c0 += 64) {
                uint32_t r0[32], r1[32];
                LDTM_X32(r0, dtm + c0);
                LDTM_X32(r1, dtm + c0 + 32);
                asm volatile("tcgen05.wait::ld.sync.aligned;" ::: "memory");
                #pragma unroll
                for (int j = 0; j < 32; j++) {
                    float mn0, mn1;
                    asm volatile("ld.shared.f32 %0, [%1];" : "=f"(mn0) : "r"(smn + 4u*(c0 + j)));
                    asm volatile("ld.shared.f32 %0, [%1];" : "=f"(mn1) : "r"(smn + 4u*(c0 + 32 + j)));
                    vmin = fminf(vmin, fmaf(-2.f, __uint_as_float(r0[j]), mn0));
                    vmin = fminf(vmin, fmaf(-2.f, __uint_as_float(r1[j]), mn1));
                }
            }
            asm volatile("tcgen05.fence::before_thread_sync;" ::: "memory");
            mbar_arrive_rank0(bFree);

            int m = mt * TILE_M + half * 256 + (int)rank * 128 + (warp & 3) * 32 + lane;
            float v = g_enorm[m] + vmin;
            atomicMin((int*)&g_pscores[m], __float_as_int(v));
        }
    }

    __syncthreads();
    CLUSTER_SYNC();
    if (warp == 12) {
        asm volatile("tcgen05.dealloc.cta_group::2.sync.aligned.b32 %0, %1;"
                     :: "r"(tmem), "r"(512u));
    }
    CLUSTER_SYNC();
#endif  // HAS_TC
}

// ================= GEMM path B: mma.sync fallback (base-arch image) ============
#define KTILE   32
#define ASTRIDE 40

__global__ void __launch_bounds__(256) k_gemm_fb() {
#if !HAS_TC
    __shared__ __align__(16) __nv_bfloat16 As[2][128 * ASTRIDE];
    __shared__ __align__(16) __nv_bfloat16 Bs[2][128 * ASTRIDE];
    __shared__ float sRed[2][128];

    int ntile = blockIdx.x, mtile = blockIdx.y;
    int tid = threadIdx.x;
    int warp = tid >> 5, lane = tid & 31;
    int wm = warp >> 1, wn = warp & 1;
    int g = lane >> 2, T = lane & 3;

    const __nv_bfloat16* gA = g_emb + (size_t)(mtile * 128) * KDIM;
    const __nv_bfloat16* gB = g_mb  + (size_t)(ntile * 128) * KDIM;

    float acc[2][8][4];
    #pragma unroll
    for (int a = 0; a < 2; a++)
        #pragma unroll
        for (int b = 0; b < 8; b++)
            #pragma unroll
            for (int c = 0; c < 4; c++) acc[a][b][c] = 0.f;

    auto issue = [&](int stage, int kc) {
        int k0 = kc * KTILE;
        #pragma unroll
        for (int it = 0; it < 2; it++) {
            int ci = tid + it * 256;
            int row = ci >> 2, seg = ci & 3;
            cp16((uint32_t)__cvta_generic_to_shared(&As[stage][row * ASTRIDE + seg * 8]),
                 gA + (size_t)row * KDIM + k0 + seg * 8);
            cp16((uint32_t)__cvta_generic_to_shared(&Bs[stage][row * ASTRIDE + seg * 8]),
                 gB + (size_t)row * KDIM + k0 + seg * 8);
        }
        asm volatile("cp.async.commit_group;\n");
    };

    issue(0, 0);
    for (int kc = 0; kc < KDIM / KTILE; kc++) {
        int cur = kc & 1;
        if (kc + 1 < KDIM / KTILE) {
            issue(cur ^ 1, kc + 1);
            asm volatile("cp.async.wait_group 1;\n");
        } else {
            asm volatile("cp.async.wait_group 0;\n");
        }
        __syncthreads();

        #pragma unroll
        for (int ks = 0; ks < 2; ks++) {
            int kk = ks * 16;
            uint32_t afr[2][4], bfr[8][2];
            #pragma unroll
            for (int mt = 0; mt < 2; mt++) {
                int r0 = wm * 32 + mt * 16 + g;
                const __nv_bfloat16* basep = &As[cur][0];
                afr[mt][0] = *(const uint32_t*)&basep[(r0)     * ASTRIDE + kk + 2 * T];
                afr[mt][1] = *(const uint32_t*)&basep[(r0 + 8) * ASTRIDE + kk + 2 * T];
                afr[mt][2] = *(const uint32_t*)&basep[(r0)     * ASTRIDE + kk + 2 * T + 8];
                afr[mt][3] = *(const uint32_t*)&basep[(r0 + 8) * ASTRIDE + kk + 2 * T + 8];
            }
            #pragma unroll
            for (int nt = 0; nt < 8; nt++) {
                int c0 = wn * 64 + nt * 8 + g;
                const __nv_bfloat16* basep = &Bs[cur][0];
                bfr[nt][0] = *(const uint32_t*)&basep[c0 * ASTRIDE + kk + 2 * T];
                bfr[nt][1] = *(const uint32_t*)&basep[c0 * ASTRIDE + kk + 2 * T + 8];
            }
            #pragma unroll
            for (int mt = 0; mt < 2; mt++)
                #pragma unroll
                for (int nt = 0; nt < 8; nt++) {
                    asm volatile(
                        "mma.sync.aligned.m16n8k16.row.col.f32.bf16.bf16.f32 "
                        "{%0,%1,%2,%3}, {%4,%5,%6,%7}, {%8,%9}, {%0,%1,%2,%3};\n"
                        : "+f"(acc[mt][nt][0]), "+f"(acc[mt][nt][1]),
                          "+f"(acc[mt][nt][2]), "+f"(acc[mt][nt][3])
                        : "r"(afr[mt][0]), "r"(afr[mt][1]), "r"(afr[mt][2]), "r"(afr[mt][3]),
                          "r"(bfr[nt][0]), "r"(bfr[nt][1]));
                }
        }
        __syncthreads();
    }

    float rmin[2][2];
    #pragma unroll
    for (int mt = 0; mt < 2; mt++) { rmin[mt][0] = 3e38f; rmin[mt][1] = 3e38f; }
    #pragma unroll
    for (int nt = 0; nt < 8; nt++) {
        int cg = ntile * 128 + wn * 64 + nt * 8 + 2 * T;
        float mn0 = g_mnorm[cg];
        float mn1 = g_mnorm[cg + 1];
        #pragma unroll
        for (int mt = 0; mt < 2; mt++) {
            rmin[mt][0] = fminf(rmin[mt][0],
                           fminf(mn0 - 2.f * acc[mt][nt][0], mn1 - 2.f * acc[mt][nt][1]));
            rmin[mt][1] = fminf(rmin[mt][1],
                           fminf(mn0 - 2.f * acc[mt][nt][2], mn1 - 2.f * acc[mt][nt][3]));
        }
    }
    #pragma unroll
    for (int mt = 0; mt < 2; mt++)
        #pragma unroll
        for (int h = 0; h < 2; h++) {
            float v = rmin[mt][h];
            v = fminf(v, __shfl_xor_sync(0xffffffffu, v, 1));
            v = fminf(v, __shfl_xor_sync(0xffffffffu, v, 2));
            rmin[mt][h] = v;
        }
    if (T == 0) {
        #pragma unroll
        for (int mt = 0; mt < 2; mt++) {
            sRed[wn][wm * 32 + mt * 16 + g]     = rmin[mt][0];
            sRed[wn][wm * 32 + mt * 16 + g + 8] = rmin[mt][1];
        }
    }
    __syncthreads();
    if (tid < 128) {
        float v = fminf(sRed[0][tid], sRed[1][tid]);
        int grow = mtile * 128 + tid;
        v += g_enorm[grow];
        atomicMin((int*)&g_pscores[grow], __float_as_int(v));
    }
#endif  // !HAS_TC
}

// ---------------- kernel: fused image scores + float4 bilinear masks ----------
__global__ void __launch_bounds__(256) k_tail(float* __restrict__ out) {
    if (blockIdx.x >= 1152) {
        int b = blockIdx.x - 1152;
        int tid = threadIdx.x;
        float m = -3e38f;
        for (int i = tid; i < 576; i += 256) m = fmaxf(m, g_pscores[b * 576 + i]);
        __shared__ float sred[256];
        sred[tid] = m; __syncthreads();
        for (int s = 128; s > 0; s >>= 1) { if (tid < s) sred[tid] = fmaxf(sred[tid], sred[tid + s]); __syncthreads(); }
        if (tid == 0) out[b] = sred[0];
        return;
    }
    int q = blockIdx.x * 256 + threadIdx.x;
    int elem = q * 4;
    int b = elem / (IMG * IMG);
    int r = elem - b * (IMG * IMG);
    int oy = r / IMG, ox = r - oy * IMG;

    float ys = (oy + 0.5f) * (1.f / 16.f) - 0.5f;
    float yf = floorf(ys);
    float wy = ys - yf;
    int y0 = max(0, min(GRIDW - 1, (int)yf));
    int y1 = max(0, min(GRIDW - 1, (int)yf + 1));
    const float* ps = g_pscores + b * 576;
    const float* r0p = ps + y0 * GRIDW;
    const float* r1p = ps + y1 * GRIDW;

    float4 res;
    float* rp = (float*)&res;
    #pragma unroll
    for (int k = 0; k < 4; k++) {
        float xs = (ox + k + 0.5f) * (1.f / 16.f) - 0.5f;
        float xf = floorf(xs);
        float wx = xs - xf;
        int x0 = max(0, min(GRIDW - 1, (int)xf));
        int x1 = max(0, min(GRIDW - 1, (int)xf + 1));
        float v00 = r0p[x0], v01 = r0p[x1];
        float v10 = r1p[x0], v11 = r1p[x1];
        rp[k] = (1.f - wy) * ((1.f - wx) * v00 + wx * v01)
              +        wy  * ((1.f - wx) * v10 + wx * v11);
    }
    *(float4*)(out + BATCH + elem) = res;
}

// ---------------- launch ----------------
extern "C" void kernel_launch(void* const* d_in, const int* in_sizes, int n_in,
                              void* d_out, int out_size) {
    const float* f6  = (const float*)d_in[0];
    const float* f8  = (const float*)d_in[1];
    const float* f10 = (const float*)d_in[2];
    const float* mb  = (const float*)d_in[3];
    float* out = (float*)d_out;

    int nsm = 148;
    cudaDeviceGetAttribute(&nsm, cudaDevAttrMultiProcessorCount, 0);
    nsm &= ~1;

    cudaFuncSetAttribute(k_pre,     cudaFuncAttributeMaxDynamicSharedMemorySize, EMB_SMEM);
    cudaFuncSetAttribute(k_gemm_tc, cudaFuncAttributeMaxDynamicSharedMemorySize, SMEM_DYN);

    // k_pre is the 2nd launch; k_gemm_tc the 4th (ncu capture window).
    k_nop<<<1, 1>>>();
    k_pre<<<PREP_BLOCKS + NPATCH, 256, EMB_SMEM>>>(f6, f8, f10, mb);
    k_gemm_fb<<<dim3(NMEM_PAD / 128, NPATCH / 128), 256>>>();
    k_gemm_tc<<<nsm, NTHREADS, SMEM_DYN>>>();
    k_tail<<<1160, 256>>>(out);
}